// round 5
// baseline (speedup 1.0000x reference)
#include <cuda_runtime.h>
#include <math.h>
#include <stdint.h>

// Problem constants (fixed shapes)
#define B_  4
#define T_  2048
#define D_  2048
#define H_  16
#define HD_ 128
#define NTOK_ (B_*T_)                 // 8192
#define SCALE_ 0.08838834764831845f   // 1/sqrt(128)

// Scratch (allocation-free rule: __device__ globals).
// Permuted-tf32 operands (uint32 payload = tf32 bit pattern).
__device__ uint32_t g_xp[NTOK_*(size_t)D_];
__device__ uint32_t g_qp[NTOK_*(size_t)D_];
__device__ uint32_t g_kp[NTOK_*(size_t)D_];
__device__ uint32_t g_vp[NTOK_*(size_t)D_];
__device__ uint32_t g_yp[NTOK_*(size_t)D_];
__device__ uint32_t g_wqp[(size_t)D_*D_];
__device__ uint32_t g_wkp[(size_t)D_*D_];
__device__ uint32_t g_wvp[(size_t)D_*D_];
__device__ uint32_t g_wop[(size_t)D_*D_];

// ===========================================================================
// Helpers
// ===========================================================================
__device__ __forceinline__ uint32_t smem_u32(const void* p) {
    uint32_t a;
    asm("{ .reg .u64 t; cvta.to.shared.u64 t, %1; cvt.u32.u64 %0, t; }"
        : "=r"(a) : "l"(p));
    return a;
}
__device__ __forceinline__ void cp16(uint32_t saddr, const void* gaddr) {
    asm volatile("cp.async.cg.shared.global [%0], [%1], 16;"
                 :: "r"(saddr), "l"(gaddr) : "memory");
}
#define CP_COMMIT() asm volatile("cp.async.commit_group;" ::: "memory")
#define CP_WAIT0()  asm volatile("cp.async.wait_group 0;" ::: "memory")
#define CP_WAIT1()  asm volatile("cp.async.wait_group 1;" ::: "memory")

__device__ __forceinline__ uint32_t f2tf32(float f) {
    uint32_t u;
    asm("cvt.rna.tf32.f32 %0, %1;" : "=r"(u) : "f"(f));
    return u;
}
__device__ __forceinline__ void mma_tf32(float c[4], uint32_t a0, uint32_t a1,
                                         uint32_t a2, uint32_t a3,
                                         uint32_t b0, uint32_t b1) {
    asm volatile(
        "mma.sync.aligned.m16n8k8.row.col.f32.tf32.tf32.f32 "
        "{%0,%1,%2,%3}, {%4,%5,%6,%7}, {%8,%9}, {%0,%1,%2,%3};"
        : "+f"(c[0]), "+f"(c[1]), "+f"(c[2]), "+f"(c[3])
        : "r"(a0), "r"(a1), "r"(a2), "r"(a3), "r"(b0), "r"(b1));
}

// Column permutation within groups of 8: stored order (0,4,1,5,2,6,3,7).
// pos(c): where logical col c is stored. inv(p): which logical col sits at p.
__device__ __forceinline__ int pcol(int c) {
    return (c & ~7) | ((c & 3) << 1) | ((c & 7) >> 2);
}
__device__ __forceinline__ int icol(int p) {
    return (p & ~7) | ((p & 7) >> 1) | ((p & 1) << 2);
}

// ===========================================================================
// Pre-convert fp32 -> permuted tf32. cols fixed = 2048.
// permRow: also permute the row (N) dim so GEMM's linear epilogue emits
// permuted layout (used for wq/wk/wv).
// ===========================================================================
__global__ void conv_perm(uint32_t* __restrict__ dst, const float* __restrict__ src,
                          int total, int permRow)
{
    int idx = blockIdx.x * blockDim.x + threadIdx.x;
    if (idx >= total) return;
    int r = idx >> 11;
    int p = idx & 2047;
    int sc = icol(p);
    int sr = permRow ? icol(r) : r;
    dst[idx] = f2tf32(src[(size_t)sr * 2048 + sc]);
}

// ===========================================================================
// tf32 mma.sync GEMM, both operands permuted tf32, K-contiguous.
// CTA 128(M) x 256(N), BK=32, 256 threads = 8 warps (2M x 4N), warp 64x64.
// smem pitch 40 -> conflict-free 64-bit fragment loads.
// Output: tf32-permuted (Ct) or plain fp32 (Cf).
// ===========================================================================
#define GP    40
#define GA_F  (128 * GP)
#define GB_F  (256 * GP)
#define GSTG  (GA_F + GB_F)
#define GEMM_SMEM_BYTES (2 * GSTG * 4)

__global__ __launch_bounds__(256)
void tt_gemm(const uint32_t* __restrict__ A, const uint32_t* __restrict__ Bw,
             float* __restrict__ Cf, uint32_t* __restrict__ Ct,
             int M, int N, int K)
{
    extern __shared__ uint32_t smu[];
    const int tid  = threadIdx.x;
    const int wid  = tid >> 5;
    const int lane = tid & 31;
    const int g    = lane >> 2;
    const int tg   = lane & 3;
    const int warpM = (wid & 1) * 64;
    const int warpN = (wid >> 1) * 64;
    const int m0 = blockIdx.y * 128;
    const int n0 = blockIdx.x * 256;

    const int lr8 = tid >> 3;
    const int lc4 = tid & 7;
    const uint32_t sbase = smem_u32(smu);

    float acc[4][8][4];
#pragma unroll
    for (int i = 0; i < 4; i++)
#pragma unroll
        for (int j = 0; j < 8; j++)
#pragma unroll
            for (int c = 0; c < 4; c++) acc[i][j][c] = 0.f;

    auto issue = [&](int ck, int s) {
        const uint32_t* Ab = A + (size_t)m0 * K + ck * 32;
        const uint32_t* Bb = Bw + (size_t)n0 * K + ck * 32;
        const uint32_t so = sbase + (uint32_t)(s * GSTG) * 4;
#pragma unroll
        for (int u = 0; u < 4; u++) {
            int r = lr8 + u * 32;
            cp16(so + (uint32_t)(r * GP + lc4 * 4) * 4, Ab + (size_t)r * K + lc4 * 4);
        }
#pragma unroll
        for (int u = 0; u < 8; u++) {
            int r = lr8 + u * 32;
            cp16(so + (uint32_t)(GA_F + r * GP + lc4 * 4) * 4, Bb + (size_t)r * K + lc4 * 4);
        }
        CP_COMMIT();
    };

    const int niter = K / 32;
    issue(0, 0);
    CP_WAIT0();
    __syncthreads();

    for (int it = 0; it < niter; it++) {
        const int cur = it & 1;
        if (it + 1 < niter) issue(it + 1, cur ^ 1);

        const uint32_t* As = smu + cur * GSTG + (warpM + g) * GP;
        const uint32_t* Bs = smu + cur * GSTG + GA_F + (warpN + g) * GP;
#pragma unroll
        for (int ks = 0; ks < 4; ks++) {
            const int cp = ks * 8 + 2 * tg;
            uint32_t af[4][4];
#pragma unroll
            for (int mi = 0; mi < 4; mi++) {
                const uint32_t* p0 = As + mi * 16 * GP + cp;
                uint2 u0 = *(const uint2*)p0;            // a0, a2 (row g)
                uint2 u1 = *(const uint2*)(p0 + 8 * GP); // a1, a3 (row g+8)
                af[mi][0] = u0.x; af[mi][1] = u1.x;
                af[mi][2] = u0.y; af[mi][3] = u1.y;
            }
            uint32_t bfr[8][2];
#pragma unroll
            for (int nj = 0; nj < 8; nj++) {
                uint2 ub = *(const uint2*)(Bs + nj * 8 * GP + cp);
                bfr[nj][0] = ub.x; bfr[nj][1] = ub.y;
            }
#pragma unroll
            for (int mi = 0; mi < 4; mi++)
#pragma unroll
                for (int nj = 0; nj < 8; nj++)
                    mma_tf32(acc[mi][nj], af[mi][0], af[mi][1], af[mi][2],
                             af[mi][3], bfr[nj][0], bfr[nj][1]);
        }

        if (it + 1 < niter) { CP_WAIT1(); } else { CP_WAIT0(); }
        __syncthreads();
    }

    if (Ct) {
#pragma unroll
        for (int mi = 0; mi < 4; mi++) {
            const int row0 = m0 + warpM + mi * 16 + g;
#pragma unroll
            for (int nj = 0; nj < 8; nj++) {
                const int col = n0 + warpN + nj * 8 + 2 * tg;
                *(uint2*)(Ct + (size_t)row0 * N + col) =
                    make_uint2(f2tf32(acc[mi][nj][0]), f2tf32(acc[mi][nj][1]));
                *(uint2*)(Ct + (size_t)(row0 + 8) * N + col) =
                    make_uint2(f2tf32(acc[mi][nj][2]), f2tf32(acc[mi][nj][3]));
            }
        }
    } else {
#pragma unroll
        for (int mi = 0; mi < 4; mi++) {
            const int row0 = m0 + warpM + mi * 16 + g;
#pragma unroll
            for (int nj = 0; nj < 8; nj++) {
                const int col = n0 + warpN + nj * 8 + 2 * tg;
                *(float2*)(Cf + (size_t)row0 * N + col) =
                    make_float2(acc[mi][nj][0], acc[mi][nj][1]);
                *(float2*)(Cf + (size_t)(row0 + 8) * N + col) =
                    make_float2(acc[mi][nj][2], acc[mi][nj][3]);
            }
        }
    }
}

// ---------------------------------------------------------------------------
// RoPE on permuted-tf32 q/k, in place. Folds SCALE_ into q.
// ---------------------------------------------------------------------------
__global__ void rope_kernel(uint32_t* __restrict__ q, uint32_t* __restrict__ k)
{
    int idx = blockIdx.x * blockDim.x + threadIdx.x;
    if (idx >= B_*T_*H_*64) return;
    int i = idx & 63;
    int h = (idx >> 6) & (H_ - 1);
    int t = (idx >> 10) & (T_ - 1);
    int b = idx >> 21;

    float ex  = (float)(2*i) * (1.0f / (float)HD_);
    float inv = powf(10000.0f, -ex);
    float ang = (float)t * inv;
    float c = cosf(ang), s = sinf(ang);

    size_t base = ((size_t)(b*T_ + t)) * D_ + h*HD_;
    size_t p1 = base + pcol(i);
    size_t p2 = base + pcol(i + 64);

    float q1 = __uint_as_float(q[p1]), q2 = __uint_as_float(q[p2]);
    q[p1] = f2tf32((q1*c - q2*s) * SCALE_);
    q[p2] = f2tf32((q2*c + q1*s) * SCALE_);
    float k1 = __uint_as_float(k[p1]), k2 = __uint_as_float(k[p2]);
    k[p1] = f2tf32(k1*c - k2*s);
    k[p2] = f2tf32(k2*c + k1*s);
}

// ===========================================================================
// Tensor-core flash attention on permuted-tf32 q/k/v, causal. Writes
// permuted-tf32 y. CTA: 64 q-rows, 256 threads (8 warps).
// Pitch 136 -> conflict-free v2 fragment loads; all cvts removed.
// ===========================================================================
#define AP  136
#define AQ_F (64*AP)
#define APP 68
#define ATTN_SMEM_BYTES ((5*AQ_F + 64*APP + 256) * 4)

__global__ __launch_bounds__(256)
void attn_mma(const uint32_t* __restrict__ q, const uint32_t* __restrict__ k,
              const uint32_t* __restrict__ v, uint32_t* __restrict__ y)
{
    extern __shared__ uint32_t smu[];
    uint32_t* Qs = smu;                    // [64][136]
    uint32_t* Ks = smu + AQ_F;             // [2][64][136]
    uint32_t* Vs = Ks + 2*AQ_F;            // [2][64][136]
    uint32_t* Ps = Vs + 2*AQ_F;            // [64][68]
    float* pmax2 = (float*)(Ps + 64*APP);  // [2][64]
    float* psum2 = pmax2 + 128;            // [2][64]

    const int qt = blockIdx.x;
    const int h  = blockIdx.y;
    const int b  = blockIdx.z;
    const int q0 = qt * 64;
    const int tid  = threadIdx.x;
    const int wid  = tid >> 5;
    const int lane = tid & 31;
    const int g    = lane >> 2;
    const int tg   = lane & 3;
    const int mt   = wid & 3;
    const int nh   = wid >> 2;

    const size_t headbase = ((size_t)b * T_) * D_ + (size_t)h * HD_;
    const uint32_t* qb = q + headbase + (size_t)q0 * D_;
    const uint32_t sQ = smem_u32(Qs);
    const uint32_t sK = smem_u32(Ks);
    const uint32_t sV = smem_u32(Vs);

    const int lr  = tid >> 5;   // 0..7
    const int lc4 = tid & 31;   // 0..31

    // Q: cp.async (uncommitted; joins first KV group)
#pragma unroll
    for (int u = 0; u < 8; u++) {
        int r = lr + u * 8;
        cp16(sQ + (uint32_t)(r * AP + lc4 * 4) * 4, qb + (size_t)r * D_ + lc4 * 4);
    }

    auto issueKV = [&](int jt, int s) {
        const uint32_t* kb = k + headbase + (size_t)(jt * 64) * D_;
        const uint32_t* vb = v + headbase + (size_t)(jt * 64) * D_;
        const uint32_t ko = sK + (uint32_t)(s * AQ_F) * 4;
        const uint32_t vo = sV + (uint32_t)(s * AQ_F) * 4;
#pragma unroll
        for (int u = 0; u < 8; u++) {
            int r = lr + u * 8;
            cp16(ko + (uint32_t)(r * AP + lc4 * 4) * 4, kb + (size_t)r * D_ + lc4 * 4);
        }
#pragma unroll
        for (int u = 0; u < 8; u++) {
            int r = lr + u * 8;
            cp16(vo + (uint32_t)(r * AP + lc4 * 4) * 4, vb + (size_t)r * D_ + lc4 * 4);
        }
        CP_COMMIT();
    };

    issueKV(0, 0);

    float oc[8][4];
#pragma unroll
    for (int nj = 0; nj < 8; nj++)
#pragma unroll
        for (int c = 0; c < 4; c++) oc[nj][c] = 0.f;
    float m0r = -1e30f, m1r = -1e30f, l0r = 0.f, l1r = 0.f;

    const int row0 = mt * 16 + g;
    const int row1 = row0 + 8;
    const uint32_t* qrow0 = Qs + row0 * AP;
    const uint32_t* qrow1 = Qs + row1 * AP;
    uint32_t* prow0 = Ps + row0 * APP;
    uint32_t* prow1 = Ps + row1 * APP;

    for (int jt = 0; jt <= qt; jt++) {
        const int cur = jt & 1;
        if (jt < qt) issueKV(jt + 1, cur ^ 1);
        if (jt < qt) { CP_WAIT1(); } else { CP_WAIT0(); }
        __syncthreads();

        const uint32_t* Kst = Ks + cur * AQ_F;
        const uint32_t* Vst = Vs + cur * AQ_F;

        // ---- S = Q @ K^T (warp: 16 x 32) ----
        float sc[4][4];
#pragma unroll
        for (int nj = 0; nj < 4; nj++)
#pragma unroll
            for (int c = 0; c < 4; c++) sc[nj][c] = 0.f;

        const uint32_t* kb0 = Kst + (nh * 32 + g) * AP;
#pragma unroll
        for (int ks = 0; ks < 16; ks++) {
            const int cp = ks * 8 + 2 * tg;
            uint2 ua0 = *(const uint2*)(qrow0 + cp);   // a0, a2
            uint2 ua1 = *(const uint2*)(qrow1 + cp);   // a1, a3
#pragma unroll
            for (int nj = 0; nj < 4; nj++) {
                uint2 ub = *(const uint2*)(kb0 + nj * 8 * AP + cp);
                mma_tf32(sc[nj], ua0.x, ua1.x, ua0.y, ua1.y, ub.x, ub.y);
            }
        }

        // ---- causal mask on diagonal tile ----
        if (jt == qt) {
#pragma unroll
            for (int nj = 0; nj < 4; nj++) {
                int colb = nh * 32 + nj * 8 + 2 * tg;
                if (colb     > row0) sc[nj][0] = -1e30f;
                if (colb + 1 > row0) sc[nj][1] = -1e30f;
                if (colb     > row1) sc[nj][2] = -1e30f;
                if (colb + 1 > row1) sc[nj][3] = -1e30f;
            }
        }

        // ---- online softmax ----
        float pm0 = -1e30f, pm1 = -1e30f;
#pragma unroll
        for (int nj = 0; nj < 4; nj++) {
            pm0 = fmaxf(pm0, fmaxf(sc[nj][0], sc[nj][1]));
            pm1 = fmaxf(pm1, fmaxf(sc[nj][2], sc[nj][3]));
        }
        pm0 = fmaxf(pm0, __shfl_xor_sync(0xffffffffu, pm0, 1));
        pm0 = fmaxf(pm0, __shfl_xor_sync(0xffffffffu, pm0, 2));
        pm1 = fmaxf(pm1, __shfl_xor_sync(0xffffffffu, pm1, 1));
        pm1 = fmaxf(pm1, __shfl_xor_sync(0xffffffffu, pm1, 2));
        if (tg == 0) {
            pmax2[nh * 64 + row0] = pm0;
            pmax2[nh * 64 + row1] = pm1;
        }
        __syncthreads();
        float mt0 = fmaxf(pmax2[row0], pmax2[64 + row0]);
        float mt1 = fmaxf(pmax2[row1], pmax2[64 + row1]);
        float mn0 = fmaxf(m0r, mt0), mn1 = fmaxf(m1r, mt1);
        float fct0 = __expf(m0r - mn0), fct1 = __expf(m1r - mn1);
        m0r = mn0; m1r = mn1;

        float ps0 = 0.f, ps1 = 0.f;
#pragma unroll
        for (int nj = 0; nj < 4; nj++) {
            float p00 = __expf(sc[nj][0] - mn0);
            float p01 = __expf(sc[nj][1] - mn0);
            float p10 = __expf(sc[nj][2] - mn1);
            float p11 = __expf(sc[nj][3] - mn1);
            ps0 += p00 + p01;
            ps1 += p10 + p11;
            int colb = nh * 32 + nj * 8 + 2 * tg;
            *(uint2*)&prow0[colb] = make_uint2(f2tf32(p00), f2tf32(p01));
            *(uint2*)&prow1[colb] = make_uint2(f2tf32(p10), f2tf32(p11));
        }
        ps0 += __shfl_xor_sync(0xffffffffu, ps0, 1);
        ps0 += __shfl_xor_sync(0xffffffffu, ps0, 2);
        ps1 += __shfl_xor_sync(0xffffffffu, ps1, 1);
        ps1 += __shfl_xor_sync(0xffffffffu, ps1, 2);
        if (tg == 0) {
            psum2[nh * 64 + row0] = ps0;
            psum2[nh * 64 + row1] = ps1;
        }
        __syncthreads();
        l0r = l0r * fct0 + psum2[row0] + psum2[64 + row0];
        l1r = l1r * fct1 + psum2[row1] + psum2[64 + row1];

#pragma unroll
        for (int nj = 0; nj < 8; nj++) {
            oc[nj][0] *= fct0; oc[nj][1] *= fct0;
            oc[nj][2] *= fct1; oc[nj][3] *= fct1;
        }

        // ---- O += P @ V (warp: 16 rows x 64 cols, permuted col space) ----
        const uint32_t* vb0 = Vst + nh * 64 + g;
#pragma unroll
        for (int ks = 0; ks < 8; ks++) {
            const int kc = ks * 8 + tg;
            uint32_t a0 = prow0[kc], a1 = prow1[kc];
            uint32_t a2 = prow0[kc + 4], a3 = prow1[kc + 4];
            const uint32_t* vk0 = vb0 + kc * AP;
            const uint32_t* vk1 = vb0 + (kc + 4) * AP;
#pragma unroll
            for (int nj = 0; nj < 8; nj++)
                mma_tf32(oc[nj], a0, a1, a2, a3, vk0[nj * 8], vk1[nj * 8]);
        }
    }

    // ---- epilogue: O /= l, write permuted tf32 ----
    float inv0 = 1.0f / l0r, inv1 = 1.0f / l1r;
    uint32_t* yb = y + headbase + (size_t)q0 * D_;
#pragma unroll
    for (int nj = 0; nj < 8; nj++) {
        int col = nh * 64 + nj * 8 + 2 * tg;
        *(uint2*)(yb + (size_t)row0 * D_ + col) =
            make_uint2(f2tf32(oc[nj][0] * inv0), f2tf32(oc[nj][1] * inv0));
        *(uint2*)(yb + (size_t)row1 * D_ + col) =
            make_uint2(f2tf32(oc[nj][2] * inv1), f2tf32(oc[nj][3] * inv1));
    }
}

// ---------------------------------------------------------------------------
extern "C" void kernel_launch(void* const* d_in, const int* in_sizes, int n_in,
                              void* d_out, int out_size)
{
    const float* x  = (const float*)d_in[0];
    const float* wq = (const float*)d_in[1];
    const float* wk = (const float*)d_in[2];
    const float* wv = (const float*)d_in[3];
    const float* wo = (const float*)d_in[4];
    float* out = (float*)d_out;

    uint32_t *xp, *qp, *kp, *vp, *yp, *wqp, *wkp, *wvp, *wop;
    cudaGetSymbolAddress((void**)&xp,  g_xp);
    cudaGetSymbolAddress((void**)&qp,  g_qp);
    cudaGetSymbolAddress((void**)&kp,  g_kp);
    cudaGetSymbolAddress((void**)&vp,  g_vp);
    cudaGetSymbolAddress((void**)&yp,  g_yp);
    cudaGetSymbolAddress((void**)&wqp, g_wqp);
    cudaGetSymbolAddress((void**)&wkp, g_wkp);
    cudaGetSymbolAddress((void**)&wvp, g_wvp);
    cudaGetSymbolAddress((void**)&wop, g_wop);

    cudaFuncSetAttribute(tt_gemm,
                         cudaFuncAttributeMaxDynamicSharedMemorySize,
                         GEMM_SMEM_BYTES);
    cudaFuncSetAttribute(attn_mma,
                         cudaFuncAttributeMaxDynamicSharedMemorySize,
                         ATTN_SMEM_BYTES);

    // Pre-convert inputs to (permuted) tf32
    const int xtot = NTOK_ * D_;
    const int wtot = D_ * D_;
    conv_perm<<<(xtot + 255) / 256, 256>>>(xp, x, xtot, 0);
    conv_perm<<<(wtot + 255) / 256, 256>>>(wqp, wq, wtot, 1);
    conv_perm<<<(wtot + 255) / 256, 256>>>(wkp, wk, wtot, 1);
    conv_perm<<<(wtot + 255) / 256, 256>>>(wvp, wv, wtot, 1);
    conv_perm<<<(wtot + 255) / 256, 256>>>(wop, wo, wtot, 0);

    dim3 gproj(D_ / 256, NTOK_ / 128);   // (8, 64)
    tt_gemm<<<gproj, 256, GEMM_SMEM_BYTES>>>(xp, wqp, nullptr, qp, NTOK_, D_, D_);
    tt_gemm<<<gproj, 256, GEMM_SMEM_BYTES>>>(xp, wkp, nullptr, kp, NTOK_, D_, D_);
    tt_gemm<<<gproj, 256, GEMM_SMEM_BYTES>>>(xp, wvp, nullptr, vp, NTOK_, D_, D_);

    int nrope = B_*T_*H_*64;
    rope_kernel<<<(nrope + 255) / 256, 256>>>(qp, kp);

    dim3 gattn(T_ / 64, H_, B_);         // (32, 16, 4)
    attn_mma<<<gattn, 256, ATTN_SMEM_BYTES>>>(qp, kp, vp, yp);

    tt_gemm<<<gproj, 256, GEMM_SMEM_BYTES>>>(yp, wop, out, nullptr, NTOK_, D_, D_);
}